// round 8
// baseline (speedup 1.0000x reference)
#include <cuda_runtime.h>
#include <cstddef>

// ---------------------------------------------------------------------------
// Problem constants (from reference):
//  B=1, C=8, O=8, G=12, X=Y=Z=12, CH=8, CW=40
//  Xo=Yo=Zo=9, N=729, GO=96, basis dim b=7
//  x       : (1, 8, 12,12,12, 8, 40) f32   strides: c=552960, x=46080, y=3840, z=320, h=40, w=1
//  weight  : (8, 8, 3,3,3, 7)       f32   o*1512 + c*189 + f*7 + b
//  bias    : (8, 3,3,3)             f32
//  basis   : (12, 7, 3, 3)          f32   g*63 + b*9 + u*3 + v
//  I, J    : (8, 40)                i32
//  T       : (12, 8, 40)            i32
//  out     : (96, 12,12,12, 8,40)   f32   go*552960 + v*320 + h*40 + w
//
// Factorized algorithm:
//  Stage1: t[n][ob][pos] = sum_{c,f} W[o,c,f,b] * x[c, n+f, pos],  ob = o*7+b (56), pos = h*40+w (320)
//  Stage2: out[g*8+o][voxel][pos] = bias_sum[o]
//            + sum_{b,u,v} basis[T[g,pos], b,u,v] * t[n][o*7+b][(I[pos]-1+u)*40 + (J[pos]-1+v)]
//          border voxels (x/y/z in {0,10,11}) -> 0
// ---------------------------------------------------------------------------

typedef unsigned long long u64;

#define T_ELEMS (729 * 56 * 320)
__device__ __align__(16) float g_t[T_ELEMS];   // 52.25 MB scratch (device global, no alloc)

__device__ __forceinline__ u64 pack2(float a, float b) {
    u64 r;
    asm("mov.b64 %0, {%1, %2};" : "=l"(r) : "f"(a), "f"(b));
    return r;
}
__device__ __forceinline__ void unpack2(u64 v, float& a, float& b) {
    asm("mov.b64 {%0, %1}, %2;" : "=f"(a), "=f"(b) : "l"(v));
}
// acc = w * x + acc   (packed fp32x2, Blackwell FFMA2 path)
__device__ __forceinline__ void ffma2(u64& acc, u64 w, u64 x) {
    asm("fma.rn.f32x2 %0, %1, %2, %0;" : "+l"(acc) : "l"(w), "l"(x));
}

// ---------------------------------------------------------------------------
// Stage 1: one CTA per n (729). 160 threads, each handles positions tid and
// tid+160. W transposed in shared to [c][f][ob] so each (c,f) step consumes
// 28 contiguous 64-bit weight pairs via packed FMA.
// ---------------------------------------------------------------------------
__global__ void __launch_bounds__(160, 2)
stage1_kernel(const float* __restrict__ x, const float* __restrict__ weight)
{
    __shared__ __align__(16) float Wsh[12096];   // [c][f][ob], 48.4 KB

    const int n   = blockIdx.x;
    const int tid = threadIdx.x;

    // Load + transpose weight: (o,c,f,b) -> [(c*27+f)*56 + o*7 + b]
    for (int i = tid; i < 12096; i += 160) {
        int o = i / 1512;  int r = i - o * 1512;
        int c = r / 189;   r -= c * 189;
        int f = r / 7;     int b = r - f * 7;
        Wsh[(c * 27 + f) * 56 + o * 7 + b] = weight[i];
    }
    __syncthreads();

    const int zi = n % 9;
    const int yi = (n / 9) % 9;
    const int xi = n / 81;

    const float* xb = x + (size_t)xi * 46080 + (size_t)yi * 3840 + (size_t)zi * 320 + tid;

    u64 acc0[28], acc1[28];
#pragma unroll
    for (int p = 0; p < 28; p++) { acc0[p] = 0ull; acc1[p] = 0ull; }

    float a0 = xb[0];
    float a1 = xb[160];

    for (int cf = 0; cf < 216; cf++) {
        // prefetch next x pair
        float nx0 = 0.f, nx1 = 0.f;
        if (cf + 1 < 216) {
            int cn = cf + 1;
            int c  = cn / 27;  int f  = cn - c * 27;
            int fi = f / 9;    int fr = f - fi * 9;
            int fj = fr / 3;   int fk = fr - fj * 3;
            int off = c * 552960 + fi * 46080 + fj * 3840 + fk * 320;
            nx0 = xb[off];
            nx1 = xb[off + 160];
        }

        u64 xx0 = pack2(a0, a0);
        u64 xx1 = pack2(a1, a1);
        const u64* wp = (const u64*)(Wsh + cf * 56);
#pragma unroll
        for (int p = 0; p < 28; p++) {
            u64 w = wp[p];
            ffma2(acc0[p], w, xx0);
            ffma2(acc1[p], w, xx1);
        }
        a0 = nx0;
        a1 = nx1;
    }

    float* tp = g_t + (size_t)n * 17920 + tid;
#pragma unroll
    for (int p = 0; p < 28; p++) {
        float lo, hi;
        unpack2(acc0[p], lo, hi);
        tp[(2 * p) * 320]           = lo;
        tp[(2 * p + 1) * 320]       = hi;
        unpack2(acc1[p], lo, hi);
        tp[(2 * p) * 320 + 160]     = lo;
        tp[(2 * p + 1) * 320 + 160] = hi;
    }
}

// ---------------------------------------------------------------------------
// Stage 2: one CTA per output voxel (1728). Border voxels -> zeros.
// Interior: t[n] (71.7 KB) in dynamic shared; per-(g) basis row in registers;
// each thread owns one (h,w) position and produces all 96 go channels.
// ---------------------------------------------------------------------------
__global__ void __launch_bounds__(320, 2)
stage2_kernel(const float* __restrict__ basis, const float* __restrict__ bias,
              const int* __restrict__ Iarr, const int* __restrict__ Jarr,
              const int* __restrict__ Tarr, float* __restrict__ out)
{
    extern __shared__ float tsh[];        // 17920 floats = 71680 B
    __shared__ float bas_sh[756];
    __shared__ float bias_sh[8];
    __shared__ int   Tsh[3840];

    const int v   = blockIdx.x;
    const int tid = threadIdx.x;
    const int zv  = v % 12;
    const int yv  = (v / 12) % 12;
    const int xv  = v / 144;

    if (xv < 1 || xv > 9 || yv < 1 || yv > 9 || zv < 1 || zv > 9) {
        // border voxel: zero all 96 channels (96*320 floats = 7680 float4)
        const float4 z = make_float4(0.f, 0.f, 0.f, 0.f);
        for (int i = tid; i < 7680; i += 320) {
            int go = i / 80;
            int r  = i - go * 80;
            float4* p = (float4*)(out + (size_t)go * 552960 + (size_t)v * 320);
            p[r] = z;
        }
        return;
    }

    const int n = (xv - 1) * 81 + (yv - 1) * 9 + (zv - 1);

    // stage t[n] into shared
    {
        const float4* src = (const float4*)(g_t + (size_t)n * 17920);
        float4* dst = (float4*)tsh;
        for (int i = tid; i < 4480; i += 320) dst[i] = src[i];
    }
    for (int i = tid; i < 756; i += 320) bas_sh[i] = basis[i];
    for (int i = tid; i < 3840; i += 320) Tsh[i] = Tarr[i];
    if (tid < 8) {
        float s = 0.f;
        for (int j = 0; j < 27; j++) s += bias[tid * 27 + j];
        bias_sh[tid] = s;
    }
    __syncthreads();

    const int ih = Iarr[tid] - 1;   // in [0,5]
    const int jw = Jarr[tid] - 1;   // in [0,37]
    const int tb = ih * 40 + jw;

    float* op = out + (size_t)v * 320 + tid;

    for (int g = 0; g < 12; g++) {
        const int tg = Tsh[g * 320 + tid];
        float bg[63];
        const float* bp = bas_sh + tg * 63;
#pragma unroll
        for (int i = 0; i < 63; i++) bg[i] = bp[i];

#pragma unroll
        for (int o = 0; o < 8; o++) {
            float s0 = 0.f, s1 = 0.f, s2 = 0.f;
#pragma unroll
            for (int b = 0; b < 7; b++) {
                const float* ts = tsh + (o * 7 + b) * 320 + tb;
#pragma unroll
                for (int vv = 0; vv < 3; vv++) {
                    s0 += bg[b * 9 + 0 + vv] * ts[vv];
                    s1 += bg[b * 9 + 3 + vv] * ts[40 + vv];
                    s2 += bg[b * 9 + 6 + vv] * ts[80 + vv];
                }
            }
            op[(size_t)(g * 8 + o) * 552960] = bias_sh[o] + (s0 + s1 + s2);
        }
    }
}

// ---------------------------------------------------------------------------
// Launch wrapper. Inputs (metadata order):
//  0: x  1: weight  2: bias  3: basis_e_h  4: I  5: J  6: T  7: bias_basis
// ---------------------------------------------------------------------------
extern "C" void kernel_launch(void* const* d_in, const int* in_sizes, int n_in,
                              void* d_out, int out_size)
{
    (void)in_sizes; (void)n_in; (void)out_size;

    const float* x      = (const float*)d_in[0];
    const float* weight = (const float*)d_in[1];
    const float* bias   = (const float*)d_in[2];
    const float* basis  = (const float*)d_in[3];
    const int*   Iarr   = (const int*)d_in[4];
    const int*   Jarr   = (const int*)d_in[5];
    const int*   Tarr   = (const int*)d_in[6];
    float*       out    = (float*)d_out;

    cudaFuncSetAttribute(stage2_kernel,
                         cudaFuncAttributeMaxDynamicSharedMemorySize, 71680);

    stage1_kernel<<<729, 160>>>(x, weight);
    stage2_kernel<<<1728, 320, 71680>>>(basis, bias, Iarr, Jarr, Tarr, out);
}

// round 10
// speedup vs baseline: 4.3897x; 4.3897x over previous
#include <cuda_runtime.h>
#include <cstddef>

// ---------------------------------------------------------------------------
//  B=1, C=8, O=8, G=12, X=Y=Z=12, CH=8, CW=40, Xo=Yo=Zo=9, N=729, GO=96, b=7
//  Stage1: t[n][ob][pos] = sum_{c,f} W[o,c,f,b] * x[c, n+f, pos]
//  Stage2: out[g*8+o][voxel][h,w] = bias_sum[o]
//            + sum_{b,u,v} basis[T[g,h,w], b,u,v] * t[n][o*7+b][(I-1+u)*40 + (J-1+v)]
// ---------------------------------------------------------------------------

typedef unsigned long long u64;

#define T_ELEMS (729 * 56 * 320)
__device__ __align__(16) float g_t[T_ELEMS];   // 52.25 MB scratch

__device__ __forceinline__ u64 pack2(float a, float b) {
    u64 r;
    asm("mov.b64 %0, {%1, %2};" : "=l"(r) : "f"(a), "f"(b));
    return r;
}
__device__ __forceinline__ void unpack2(u64 v, float& a, float& b) {
    asm("mov.b64 {%0, %1}, %2;" : "=f"(a), "=f"(b) : "l"(v));
}
__device__ __forceinline__ void ffma2(u64& acc, u64 w, u64 x) {
    asm("fma.rn.f32x2 %0, %1, %2, %0;" : "+l"(acc) : "l"(w), "l"(x));
}

// ---------------------------------------------------------------------------
// Stage 1: one CTA per n (729). 320 threads, one position each.
// Weights transposed in shared to [c][f][ob]; read as 128-bit broadcasts.
// 28 packed f32x2 accumulators per thread (ob pairs).
// ---------------------------------------------------------------------------
__global__ void __launch_bounds__(320, 2)
stage1_kernel(const float* __restrict__ x, const float* __restrict__ weight)
{
    __shared__ __align__(16) float Wsh[12096];   // [c][f][ob]
    __shared__ int off_sh[216];

    const int n   = blockIdx.x;
    const int tid = threadIdx.x;

    // transpose weight: (o,c,f,b) -> [(c*27+f)*56 + o*7 + b]
    for (int i = tid; i < 12096; i += 320) {
        int o = i / 1512;  int r = i - o * 1512;
        int c = r / 189;   r -= c * 189;
        int f = r / 7;     int b = r - f * 7;
        Wsh[(c * 27 + f) * 56 + o * 7 + b] = weight[i];
    }
    if (tid < 216) {
        int c  = tid / 27;  int f  = tid - c * 27;
        int fi = f / 9;     int fr = f - fi * 9;
        int fj = fr / 3;    int fk = fr - fj * 3;
        off_sh[tid] = c * 552960 + fi * 46080 + fj * 3840 + fk * 320;
    }
    __syncthreads();

    const int zi = n % 9;
    const int yi = (n / 9) % 9;
    const int xi = n / 81;
    const float* xb = x + (size_t)xi * 46080 + (size_t)yi * 3840 + (size_t)zi * 320 + tid;

    u64 acc[28];
#pragma unroll
    for (int p = 0; p < 28; p++) acc[p] = 0ull;

    // depth-2 prefetch of x
    float a_c = xb[0];
    float a_n = xb[off_sh[1]];

    for (int cf = 0; cf < 216; cf++) {
        float a_2 = 0.f;
        if (cf + 2 < 216) a_2 = xb[off_sh[cf + 2]];

        u64 xx = pack2(a_c, a_c);
        const ulonglong2* wp = (const ulonglong2*)(Wsh + cf * 56);
#pragma unroll
        for (int p = 0; p < 14; p++) {
            ulonglong2 ww = wp[p];
            ffma2(acc[2 * p],     ww.x, xx);
            ffma2(acc[2 * p + 1], ww.y, xx);
        }
        a_c = a_n;
        a_n = a_2;
    }

    float* tp = g_t + (size_t)n * 17920 + tid;
#pragma unroll
    for (int q = 0; q < 28; q++) {
        float lo, hi;
        unpack2(acc[q], lo, hi);
        tp[(2 * q) * 320]     = lo;   // ob = 2q
        tp[(2 * q + 1) * 320] = hi;   // ob = 2q+1
    }
}

// ---------------------------------------------------------------------------
// Stage 2: one CTA per output voxel (1728), 320 threads.
// Thread = (og, hh, w): og=tid/160 -> o in {4og..4og+3}; hh=0..3 -> rows
// (2hh, 2hh+1); w=0..39. The two rows' 3x3 windows share a 4-row x 3-col
// shared-memory window (12 conflict-free LDS). g processed in chunks of 2
// with basis rows register-cached. No large register arrays -> no spills.
// ---------------------------------------------------------------------------
__global__ void __launch_bounds__(320, 2)
stage2_kernel(const float* __restrict__ basis, const float* __restrict__ bias,
              const int* __restrict__ Iarr, const int* __restrict__ Jarr,
              const int* __restrict__ Tarr, float* __restrict__ out)
{
    extern __shared__ float tsh[];        // 17920 floats = 71680 B
    __shared__ float bas_sh[756];
    __shared__ float bias_sh[8];

    const int v   = blockIdx.x;
    const int tid = threadIdx.x;
    const int zv  = v % 12;
    const int yv  = (v / 12) % 12;
    const int xv  = v / 144;

    if (xv < 1 || xv > 9 || yv < 1 || yv > 9 || zv < 1 || zv > 9) {
        const float4 z = make_float4(0.f, 0.f, 0.f, 0.f);
        for (int i = tid; i < 7680; i += 320) {
            int go = i / 80;
            int r  = i - go * 80;
            float4* p = (float4*)(out + (size_t)go * 552960 + (size_t)v * 320);
            p[r] = z;
        }
        return;
    }

    const int n = (xv - 1) * 81 + (yv - 1) * 9 + (zv - 1);

    {
        const float4* src = (const float4*)(g_t + (size_t)n * 17920);
        float4* dst = (float4*)tsh;
        for (int i = tid; i < 4480; i += 320) dst[i] = src[i];
    }
    for (int i = tid; i < 756; i += 320) bas_sh[i] = basis[i];
    if (tid < 8) {
        float s = 0.f;
        for (int j = 0; j < 27; j++) s += bias[tid * 27 + j];
        bias_sh[tid] = s;
    }
    __syncthreads();

    const int og  = tid / 160;          // 0..1 -> o base
    const int rem = tid - og * 160;
    const int hh  = rem / 40;           // 0..3
    const int w   = rem - hh * 40;      // 0..39
    const int o0  = og * 4;
    const int h0  = 2 * hh;
    const int h1  = h0 + 1;
    const int p0  = h0 * 40 + w;
    const int p1  = p0 + 40;

    const int jw = Jarr[p0] - 1;                 // 0..37 (J depends on w only)
    const int I0 = Iarr[p0];
    const int I1 = Iarr[p1];
    const int su = I1 - I0;                      // 0 or 1
    const int r0row = I0 - 1;

    // 4-row window byte bases (row*40 + jw), row clamped to 7
    int rro[4];
#pragma unroll
    for (int j = 0; j < 4; j++) {
        int rrj = r0row + j;
        if (rrj > 7) rrj = 7;
        rro[j] = rrj * 40 + jw;
    }

    float* op0 = out + (size_t)v * 320 + p0;

    for (int gc = 0; gc < 6; gc++) {
        // per-g gather indices (fully data-driven from T input)
        int tg0[2], tg1[2];
#pragma unroll
        for (int gg = 0; gg < 2; gg++) {
            int g = gc * 2 + gg;
            tg0[gg] = Tarr[g * 320 + p0];
            tg1[gg] = Tarr[g * 320 + p1];
        }

        float acc0[2][4], acc1[2][4];
#pragma unroll
        for (int gg = 0; gg < 2; gg++)
#pragma unroll
            for (int oo = 0; oo < 4; oo++) { acc0[gg][oo] = 0.f; acc1[gg][oo] = 0.f; }

        for (int b = 0; b < 7; b++) {
            float bg0[2][9], bg1[2][9];
#pragma unroll
            for (int gg = 0; gg < 2; gg++) {
                const float* q0 = bas_sh + tg0[gg] * 63 + b * 9;
                const float* q1 = bas_sh + tg1[gg] * 63 + b * 9;
#pragma unroll
                for (int i = 0; i < 9; i++) { bg0[gg][i] = q0[i]; bg1[gg][i] = q1[i]; }
            }

#pragma unroll
            for (int oo = 0; oo < 4; oo++) {
                const float* tb = tsh + ((o0 + oo) * 7 + b) * 320;
                float win[4][3];
#pragma unroll
                for (int j = 0; j < 4; j++) {
#pragma unroll
                    for (int vv = 0; vv < 3; vv++)
                        win[j][vv] = tb[rro[j] + vv];
                }
                // shifted window for the second row's position
                float ws[3][3];
#pragma unroll
                for (int u = 0; u < 3; u++)
#pragma unroll
                    for (int vv = 0; vv < 3; vv++)
                        ws[u][vv] = su ? win[u + 1][vv] : win[u][vv];

#pragma unroll
                for (int gg = 0; gg < 2; gg++) {
#pragma unroll
                    for (int u = 0; u < 3; u++)
#pragma unroll
                        for (int vv = 0; vv < 3; vv++) {
                            acc0[gg][oo] += bg0[gg][u * 3 + vv] * win[u][vv];
                            acc1[gg][oo] += bg1[gg][u * 3 + vv] * ws[u][vv];
                        }
                }
            }
        }

        // write 16 outputs (2 g x 4 o x 2 positions)
#pragma unroll
        for (int gg = 0; gg < 2; gg++) {
            int g = gc * 2 + gg;
#pragma unroll
            for (int oo = 0; oo < 4; oo++) {
                int o = o0 + oo;
                float bs = bias_sh[o];
                float* dst = op0 + (size_t)(g * 8 + o) * 552960;
                dst[0]  = acc0[gg][oo] + bs;
                dst[40] = acc1[gg][oo] + bs;
            }
        }
    }
}

// ---------------------------------------------------------------------------
extern "C" void kernel_launch(void* const* d_in, const int* in_sizes, int n_in,
                              void* d_out, int out_size)
{
    (void)in_sizes; (void)n_in; (void)out_size;

    const float* x      = (const float*)d_in[0];
    const float* weight = (const float*)d_in[1];
    const float* bias   = (const float*)d_in[2];
    const float* basis  = (const float*)d_in[3];
    const int*   Iarr   = (const int*)d_in[4];
    const int*   Jarr   = (const int*)d_in[5];
    const int*   Tarr   = (const int*)d_in[6];
    float*       out    = (float*)d_out;

    cudaFuncSetAttribute(stage2_kernel,
                         cudaFuncAttributeMaxDynamicSharedMemorySize, 71680);

    stage1_kernel<<<729, 320>>>(x, weight);
    stage2_kernel<<<1728, 320, 71680>>>(basis, bias, Iarr, Jarr, Tarr, out);
}